// round 4
// baseline (speedup 1.0000x reference)
#include <cuda_runtime.h>

#define BB 4
#define LL 512
#define DD 128
#define BL (BB*LL)
#define TI 4

// Scratch (device globals; no allocation)
__device__ float g_E[BL*DD];                 // exp2(2*log2e * (inp @ Wu^T))  indexed by j
__device__ float g_F[BL*DD];                 // exp2(2*log2e * (inp @ Ww^T))  indexed by i
__device__ float g_attn_scratch[BB*LL*LL];   // used only if harness doesn't want attn

__device__ __forceinline__ float ex2a(float x){ float y; asm("ex2.approx.ftz.f32 %0, %1;" : "=f"(y) : "f"(x)); return y; }
__device__ __forceinline__ float rcpa(float x){ float y; asm("rcp.approx.ftz.f32 %0, %1;" : "=f"(y) : "f"(x)); return y; }

// ---------------------------------------------------------------------------
// Kernel A: qu = inp @ Wu^T, kw = inp @ Ww^T ; store E=exp2(K*qu), F=exp2(K*kw)
// grid (BL/16, 2), block 128. blockIdx.y selects Wu->g_E vs Ww->g_F.
// ---------------------------------------------------------------------------
__global__ __launch_bounds__(128) void proj_kernel(const float* __restrict__ inp,
                                                   const float* __restrict__ Wu,
                                                   const float* __restrict__ Ww){
    __shared__ __align__(16) float sW[128*33];
    __shared__ __align__(16) float sI[16*33];
    const float* W  = blockIdx.y ? Ww  : Wu;
    float*       dst = blockIdx.y ? g_F : g_E;
    const int r0  = blockIdx.x * 16;
    const int tid = threadIdx.x;

    float acc[16];
    #pragma unroll
    for (int r = 0; r < 16; r++) acc[r] = 0.f;

    for (int dc = 0; dc < 128; dc += 32){
        for (int idx = tid; idx < 128*32; idx += 128){
            int t = idx >> 5, c = idx & 31;
            sW[t*33 + c] = W[t*128 + dc + c];
        }
        for (int idx = tid; idx < 16*32; idx += 128){
            int r = idx >> 5, c = idx & 31;
            sI[r*33 + c] = inp[(r0 + r)*128 + dc + c];
        }
        __syncthreads();
        #pragma unroll 8
        for (int c = 0; c < 32; c++){
            float w = sW[tid*33 + c];            // lanes stride-33 -> conflict-free
            #pragma unroll
            for (int r = 0; r < 16; r++) acc[r] += sI[r*33 + c] * w;   // broadcast
        }
        __syncthreads();
    }
    const float K = 2.8853900817779268f;  // 2*log2(e)
    #pragma unroll
    for (int r = 0; r < 16; r++)
        dst[(r0 + r)*128 + tid] = ex2a(K * acc[r]);
}

// ---------------------------------------------------------------------------
// Kernel B: fused scores + softmax + attn write + out = attn @ inp
// grid BL/TI = 512 blocks, block 256. Block owns (b, i0..i0+3).
// score[i][j] = Cwv - 2 * sum_d wv[d] * rcp(1 + E[j,d]*F[i,d])
// ---------------------------------------------------------------------------
__global__ __launch_bounds__(256) void attn_kernel(const float* __restrict__ inp,
                                                   const float* __restrict__ wvp,
                                                   float* __restrict__ out,
                                                   float* __restrict__ attn){
    __shared__ __align__(16) float sE [64*132];     // E chunk (pad 132 -> conflict-free f4)
    __shared__ __align__(16) float sF [TI*128];
    __shared__ __align__(16) float swv[128];
    __shared__ __align__(16) float sp [TI*4*64];    // partial sums
    __shared__ __align__(16) float ss [TI*512];     // scores -> attn row cache
    const int tid = threadIdx.x;
    const int b   = blockIdx.x >> 7;                // /128
    const int i0  = (blockIdx.x & 127) * TI;

    if (tid < 128) swv[tid] = wvp[tid];
    for (int idx = tid; idx < TI*128; idx += 256)
        sF[idx] = g_F[(b*LL + i0 + (idx >> 7))*128 + (idx & 127)];
    __syncthreads();

    float cw = 0.f;
    for (int d2 = 0; d2 < 128; d2++) cw += swv[d2];  // broadcast reads, cheap

    const int jj = tid & 63;       // j within chunk
    const int q  = tid >> 6;       // d-quarter (0..3)

    // ---------------- scores ----------------
    for (int ch = 0; ch < 8; ch++){
        const int j0 = ch * 64;
        for (int idx = tid; idx < 64*32; idx += 256){
            int r = idx >> 5, c = idx & 31;
            *(float4*)&sE[r*132 + c*4] =
                *(const float4*)&g_E[(b*LL + j0 + r)*128 + c*4];
        }
        __syncthreads();
        #pragma unroll
        for (int i = 0; i < TI; i++){
            float a = 0.f;
            const float* Er = &sE [jj*132 + q*32];
            const float* Fr = &sF [i*128  + q*32];
            const float* Wr = &swv[         q*32];
            #pragma unroll
            for (int dd = 0; dd < 32; dd += 4){
                float4 ev = *(const float4*)(Er + dd);
                float4 fv = *(const float4*)(Fr + dd);
                float4 wv = *(const float4*)(Wr + dd);
                a += wv.x * rcpa(1.f + ev.x*fv.x);
                a += wv.y * rcpa(1.f + ev.y*fv.y);
                a += wv.z * rcpa(1.f + ev.z*fv.z);
                a += wv.w * rcpa(1.f + ev.w*fv.w);
            }
            sp[(i*4 + q)*64 + jj] = a;
        }
        __syncthreads();
        {   // 256 threads = 4 i  x 64 j : reduce the 4 d-quarters
            float s = sp[(q*4+0)*64+jj] + sp[(q*4+1)*64+jj]
                    + sp[(q*4+2)*64+jj] + sp[(q*4+3)*64+jj];
            ss[q*512 + j0 + jj] = cw - 2.f * s;
        }
        __syncthreads();
    }

    // ---------------- softmax over j (one warp per i) ----------------
    const int w = tid >> 5, lane = tid & 31;
    if (w < TI){
        float m = -1e30f;
        #pragma unroll
        for (int k = 0; k < 16; k++) m = fmaxf(m, ss[w*512 + lane + k*32]);
        #pragma unroll
        for (int o = 16; o > 0; o >>= 1) m = fmaxf(m, __shfl_xor_sync(0xffffffffu, m, o));
        const float L2E = 1.4426950408889634f;
        float sum = 0.f;
        #pragma unroll
        for (int k = 0; k < 16; k++){
            float e = ex2a((ss[w*512 + lane + k*32] - m) * L2E);
            ss[w*512 + lane + k*32] = e;
            sum += e;
        }
        #pragma unroll
        for (int o = 16; o > 0; o >>= 1) sum += __shfl_xor_sync(0xffffffffu, sum, o);
        float inv = 1.0f / sum;   // accurate div, only 2048 total
        #pragma unroll
        for (int k = 0; k < 16; k++){
            float a = ss[w*512 + lane + k*32] * inv;
            ss[w*512 + lane + k*32] = a;
            attn[(b*LL + i0 + w)*LL + lane + k*32] = a;
        }
    }
    __syncthreads();

    // ---------------- out = attn @ inp ----------------
    const int d = tid & 127, g = tid >> 7;     // g in {0,1}; rows g and g+2
    float a0 = 0.f, a1 = 0.f;
    for (int ch = 0; ch < 8; ch++){
        const int j0 = ch * 64;
        for (int idx = tid; idx < 64*32; idx += 256){
            int r = idx >> 5, c = idx & 31;
            *(float4*)&sE[r*132 + c*4] =
                *(const float4*)&inp[(b*LL + j0 + r)*128 + c*4];
        }
        __syncthreads();
        #pragma unroll 8
        for (int j = 0; j < 64; j++){
            float v = sE[j*132 + d];
            a0 += ss[ g     *512 + j0 + j] * v;
            a1 += ss[(g + 2)*512 + j0 + j] * v;
        }
        __syncthreads();
    }
    out[(b*LL + i0 + g    )*128 + d] = a0;
    out[(b*LL + i0 + g + 2)*128 + d] = a1;
}

// ---------------------------------------------------------------------------
extern "C" void kernel_launch(void* const* d_in, const int* in_sizes, int n_in,
                              void* d_out, int out_size){
    const float* inp = (const float*)d_in[0];
    const float* Wu  = (const float*)d_in[1];
    const float* Ww  = (const float*)d_in[2];
    const float* Wv  = (const float*)d_in[3];
    float* out = (float*)d_out;

    float* attn;
    if (out_size >= BB*LL*DD + BB*LL*LL){
        attn = out + BB*LL*DD;               // tuple layout: [out | attn]
    } else {
        void* p = nullptr;
        cudaGetSymbolAddress(&p, g_attn_scratch);
        attn = (float*)p;
    }

    proj_kernel<<<dim3(BL/16, 2), 128>>>(inp, Wu, Ww);
    attn_kernel<<<BL/TI, 256>>>(inp, Wv, out, attn);
}

// round 5
// speedup vs baseline: 1.0462x; 1.0462x over previous
#include <cuda_runtime.h>

#define BB 4
#define LL 512
#define DD 128
#define BL (BB*LL)
#define TI 4
#define CH 32          // j rows per staged chunk

// Scratch (device globals; no allocation)
__device__ float g_E[BL*DD];                 // exp2(2*log2e * (inp @ Wu^T))  indexed by j
__device__ float g_F[BL*DD];                 // exp2(2*log2e * (inp @ Ww^T))  indexed by i
__device__ float g_attn_scratch[BB*LL*LL];   // used only if harness doesn't want attn

__device__ __forceinline__ float ex2a(float x){ float y; asm("ex2.approx.ftz.f32 %0, %1;" : "=f"(y) : "f"(x)); return y; }
__device__ __forceinline__ float rcpa(float x){ float y; asm("rcp.approx.ftz.f32 %0, %1;" : "=f"(y) : "f"(x)); return y; }

// ---------------------------------------------------------------------------
// Kernel A: qu = inp @ Wu^T, kw = inp @ Ww^T ; store E=exp2(K*qu), F=exp2(K*kw)
// grid (BL/16, 2), block 128. blockIdx.y selects Wu->g_E vs Ww->g_F.
// ---------------------------------------------------------------------------
__global__ __launch_bounds__(128) void proj_kernel(const float* __restrict__ inp,
                                                   const float* __restrict__ Wu,
                                                   const float* __restrict__ Ww){
    __shared__ __align__(16) float sW[128*33];
    __shared__ __align__(16) float sI[16*33];
    const float* W  = blockIdx.y ? Ww  : Wu;
    float*       dst = blockIdx.y ? g_F : g_E;
    const int r0  = blockIdx.x * 16;
    const int tid = threadIdx.x;

    float acc[16];
    #pragma unroll
    for (int r = 0; r < 16; r++) acc[r] = 0.f;

    for (int dc = 0; dc < 128; dc += 32){
        for (int idx = tid; idx < 128*32; idx += 128){
            int t = idx >> 5, c = idx & 31;
            sW[t*33 + c] = W[t*128 + dc + c];
        }
        for (int idx = tid; idx < 16*32; idx += 128){
            int r = idx >> 5, c = idx & 31;
            sI[r*33 + c] = inp[(r0 + r)*128 + dc + c];
        }
        __syncthreads();
        #pragma unroll 8
        for (int c = 0; c < 32; c++){
            float w = sW[tid*33 + c];            // lanes stride-33 -> conflict-free
            #pragma unroll
            for (int r = 0; r < 16; r++) acc[r] += sI[r*33 + c] * w;   // broadcast
        }
        __syncthreads();
    }
    const float K = 2.8853900817779268f;  // 2*log2(e)
    #pragma unroll
    for (int r = 0; r < 16; r++)
        dst[(r0 + r)*128 + tid] = ex2a(K * acc[r]);
}

// ---------------------------------------------------------------------------
// Kernel B: fused scores + softmax + attn write + out = attn @ inp
// grid BL/TI = 512 blocks, block 256, forced 4 blocks/SM (single wave on 148 SMs).
// score[i][j] = Cwv - 2 * sum_d wv[d] * rcp(1 + E[j,d]*F[i,d])
// Thread map (score): jj = tid&31 (j within chunk), q = tid>>5 (16-wide d group).
// ---------------------------------------------------------------------------
__global__ __launch_bounds__(256, 4) void attn_kernel(const float* __restrict__ inp,
                                                      const float* __restrict__ wvp,
                                                      float* __restrict__ out,
                                                      float* __restrict__ attn){
    __shared__ __align__(16) float sE [CH*132];     // E / inp chunk (pad 132)
    __shared__ __align__(16) float sF [TI*128];
    __shared__ __align__(16) float swv[128];
    __shared__ __align__(16) float sp [TI*8*32];    // partial sums per d-group
    __shared__ __align__(16) float ss [TI*512];     // scores -> attn row cache
    const int tid = threadIdx.x;
    const int b   = blockIdx.x >> 7;                // /128
    const int i0  = (blockIdx.x & 127) * TI;
    const int lane = tid & 31;

    if (tid < 128) swv[tid] = wvp[tid];
    for (int idx = tid; idx < TI*128; idx += 256)
        sF[idx] = g_F[(b*LL + i0 + (idx >> 7))*128 + (idx & 127)];
    __syncthreads();

    // cw = sum(wv) via shuffle reduction
    float cw = swv[lane] + swv[lane+32] + swv[lane+64] + swv[lane+96];
    #pragma unroll
    for (int o = 16; o > 0; o >>= 1) cw += __shfl_xor_sync(0xffffffffu, cw, o);

    const int jj = tid & 31;       // j within chunk
    const int q  = tid >> 5;       // d-group of 16 (0..7)

    // ---------------- scores ----------------
    #pragma unroll 1
    for (int ch = 0; ch < LL/CH; ch++){
        const int j0 = ch * CH;
        #pragma unroll
        for (int idx = tid; idx < CH*32; idx += 256){
            int r = idx >> 5, c = idx & 31;
            *(float4*)&sE[r*132 + c*4] =
                *(const float4*)&g_E[(b*LL + j0 + r)*128 + c*4];
        }
        __syncthreads();

        const float* Er = &sE[jj*132 + q*16];
        float4 e0 = *(const float4*)(Er +  0);
        float4 e1 = *(const float4*)(Er +  4);
        float4 e2 = *(const float4*)(Er +  8);
        float4 e3 = *(const float4*)(Er + 12);

        #pragma unroll
        for (int i = 0; i < TI; i++){
            const float* Fr = &sF [i*128 + q*16];
            const float* Wr = &swv[        q*16];
            float4 f0 = *(const float4*)(Fr +  0);
            float4 f1 = *(const float4*)(Fr +  4);
            float4 f2 = *(const float4*)(Fr +  8);
            float4 f3 = *(const float4*)(Fr + 12);
            float4 w0 = *(const float4*)(Wr +  0);
            float4 w1 = *(const float4*)(Wr +  4);
            float4 w2 = *(const float4*)(Wr +  8);
            float4 w3 = *(const float4*)(Wr + 12);
            // 4 independent accumulator chains
            float a0 = w0.x * rcpa(fmaf(e0.x, f0.x, 1.f));
            float a1 = w0.y * rcpa(fmaf(e0.y, f0.y, 1.f));
            float a2 = w0.z * rcpa(fmaf(e0.z, f0.z, 1.f));
            float a3 = w0.w * rcpa(fmaf(e0.w, f0.w, 1.f));
            a0 = fmaf(w1.x, rcpa(fmaf(e1.x, f1.x, 1.f)), a0);
            a1 = fmaf(w1.y, rcpa(fmaf(e1.y, f1.y, 1.f)), a1);
            a2 = fmaf(w1.z, rcpa(fmaf(e1.z, f1.z, 1.f)), a2);
            a3 = fmaf(w1.w, rcpa(fmaf(e1.w, f1.w, 1.f)), a3);
            a0 = fmaf(w2.x, rcpa(fmaf(e2.x, f2.x, 1.f)), a0);
            a1 = fmaf(w2.y, rcpa(fmaf(e2.y, f2.y, 1.f)), a1);
            a2 = fmaf(w2.z, rcpa(fmaf(e2.z, f2.z, 1.f)), a2);
            a3 = fmaf(w2.w, rcpa(fmaf(e2.w, f2.w, 1.f)), a3);
            a0 = fmaf(w3.x, rcpa(fmaf(e3.x, f3.x, 1.f)), a0);
            a1 = fmaf(w3.y, rcpa(fmaf(e3.y, f3.y, 1.f)), a1);
            a2 = fmaf(w3.z, rcpa(fmaf(e3.z, f3.z, 1.f)), a2);
            a3 = fmaf(w3.w, rcpa(fmaf(e3.w, f3.w, 1.f)), a3);
            sp[(i*8 + q)*32 + jj] = (a0 + a1) + (a2 + a3);
        }
        __syncthreads();
        if (tid < TI*32){
            const int i = tid >> 5, j = tid & 31;
            float s = 0.f;
            #pragma unroll
            for (int q2 = 0; q2 < 8; q2++) s += sp[(i*8 + q2)*32 + j];
            ss[i*512 + j0 + j] = cw - 2.f * s;
        }
        __syncthreads();
    }

    // ---------------- softmax over j (one warp per i) ----------------
    const int w = tid >> 5;
    if (w < TI){
        float m = -1e30f;
        #pragma unroll
        for (int k = 0; k < 16; k++) m = fmaxf(m, ss[w*512 + lane + k*32]);
        #pragma unroll
        for (int o = 16; o > 0; o >>= 1) m = fmaxf(m, __shfl_xor_sync(0xffffffffu, m, o));
        const float L2E = 1.4426950408889634f;
        float sum = 0.f;
        #pragma unroll
        for (int k = 0; k < 16; k++){
            float e = ex2a((ss[w*512 + lane + k*32] - m) * L2E);
            ss[w*512 + lane + k*32] = e;
            sum += e;
        }
        #pragma unroll
        for (int o = 16; o > 0; o >>= 1) sum += __shfl_xor_sync(0xffffffffu, sum, o);
        float inv = 1.0f / sum;   // accurate div, only 2048 total
        #pragma unroll
        for (int k = 0; k < 16; k++){
            float a = ss[w*512 + lane + k*32] * inv;
            ss[w*512 + lane + k*32] = a;
            attn[(b*LL + i0 + w)*LL + lane + k*32] = a;
        }
    }
    __syncthreads();

    // ---------------- out = attn @ inp ----------------
    const int d = tid & 127, g = tid >> 7;     // g in {0,1}; rows g and g+2
    float a0 = 0.f, a1 = 0.f;
    #pragma unroll 1
    for (int ch = 0; ch < LL/CH; ch++){
        const int j0 = ch * CH;
        #pragma unroll
        for (int idx = tid; idx < CH*32; idx += 256){
            int r = idx >> 5, c = idx & 31;
            *(float4*)&sE[r*132 + c*4] =
                *(const float4*)&inp[(b*LL + j0 + r)*128 + c*4];
        }
        __syncthreads();
        #pragma unroll 8
        for (int j = 0; j < CH; j++){
            float v = sE[j*132 + d];
            a0 = fmaf(ss[ g     *512 + j0 + j], v, a0);
            a1 = fmaf(ss[(g + 2)*512 + j0 + j], v, a1);
        }
        __syncthreads();
    }
    out[(b*LL + i0 + g    )*128 + d] = a0;
    out[(b*LL + i0 + g + 2)*128 + d] = a1;
}

// ---------------------------------------------------------------------------
extern "C" void kernel_launch(void* const* d_in, const int* in_sizes, int n_in,
                              void* d_out, int out_size){
    const float* inp = (const float*)d_in[0];
    const float* Wu  = (const float*)d_in[1];
    const float* Ww  = (const float*)d_in[2];
    const float* Wv  = (const float*)d_in[3];
    float* out = (float*)d_out;

    float* attn;
    if (out_size >= BB*LL*DD + BB*LL*LL){
        attn = out + BB*LL*DD;               // tuple layout: [out | attn]
    } else {
        void* p = nullptr;
        cudaGetSymbolAddress(&p, g_attn_scratch);
        attn = (float*)p;
    }

    proj_kernel<<<dim3(BL/16, 2), 128>>>(inp, Wu, Ww);
    attn_kernel<<<BL/TI, 256>>>(inp, Wv, out, attn);
}